// round 16
// baseline (speedup 1.0000x reference)
#include <cuda_runtime.h>
#include <cuda_fp16.h>
#include <math.h>

#define NB 512
#define NT 64
#define NS 30
#define ND 200
#define NH 200
#define NA 12
#define NE 1024
#define OUTC 380
#define R 16
#define NCTA (NB / R)   // 32

// MMA tilings (m16n8k16)
#define KS_GRU 26
#define NTI_GRU 76
#define KS_IO  14
#define NTI_IO 50
#define KS_EF  14
#define NTI_EF 16
#define KS_PRE 64
#define NTI_PRE 25

// scan dynamic smem layout (bytes)
#define OFF_XA    0                     // unsigned[16*216]
#define OFF_HA    13824                 // unsigned[16*116]
#define OFF_HOA   21248                 // unsigned[16*116]
#define OFF_GATES 28672                 // float[16*608]
#define OFF_DET   67584                 // float[16*200]
#define OFF_STAT  80384                 // float[16*128]
#define OFF_PI    88576                 // float[200*16]
#define OFF_PO    101376                // float[200*16]
#define OFF_STOCH 114176                // float[32*16]
#define SMEM_BYTES 116224

// ---------------- device-global scratch (allocation-free rule) ----------------
__device__ __align__(16) uint2 g_WB_gru[NTI_GRU * KS_GRU * 32];
__device__ __align__(16) uint2 g_WB_io [NTI_IO  * KS_IO  * 32];
__device__ __align__(16) uint2 g_WB_ef [NTI_EF  * KS_EF  * 32];
__device__ __align__(16) uint2 g_WB_pre[NTI_PRE * KS_PRE * 32];
__device__ float g_pre_inp[NB * NT * NH];
__device__ float g_pre_obs[NB * NT * NH];

typedef unsigned long long ull;

// ---------------- helpers ----------------
__device__ __forceinline__ unsigned h2(float a, float b) {
    __half2 h = __floats2half2_rn(a, b);
    return *(unsigned*)&h;
}
__device__ __forceinline__ ull pack2(float lo, float hi) {
    ull r; asm("mov.b64 %0, {%1, %2};" : "=l"(r) : "f"(lo), "f"(hi)); return r;
}
__device__ __forceinline__ void unpack2(ull v, float& lo, float& hi) {
    asm("mov.b64 {%0, %1}, %2;" : "=f"(lo), "=f"(hi) : "l"(v));
}
__device__ __forceinline__ ull fma2(ull a, ull b, ull c) {
    ull d; asm("fma.rn.f32x2 %0, %1, %2, %3;" : "=l"(d) : "l"(a), "l"(b), "l"(c)); return d;
}
__device__ __forceinline__ void mma16816(float& c0, float& c1, float& c2, float& c3,
                                         unsigned a0, unsigned a1, unsigned a2, unsigned a3,
                                         unsigned b0, unsigned b1) {
    asm volatile(
        "mma.sync.aligned.m16n8k16.row.col.f32.f16.f16.f32 "
        "{%0,%1,%2,%3},{%4,%5,%6,%7},{%8,%9},{%0,%1,%2,%3};"
        : "+f"(c0), "+f"(c1), "+f"(c2), "+f"(c3)
        : "r"(a0), "r"(a1), "r"(a2), "r"(a3), "r"(b0), "r"(b1));
}
__device__ __forceinline__ float eluf(float z)      { return z > 0.f ? z : expm1f(z); }
__device__ __forceinline__ float sigmoidf_(float z) { return 1.f / (1.f + expf(-z)); }
__device__ __forceinline__ float softplusf_(float z){ return fmaxf(z, 0.f) + log1pf(expf(-fabsf(z))); }

// =====================================================================
// Kernel 0: pack ALL weights into HMMA B-fragment lane order
// =====================================================================
__global__ void convert_kernel(const float* __restrict__ gru_W,
                               const float* __restrict__ gru_b,
                               const float* __restrict__ img_W,
                               const float* __restrict__ img_out_b,
                               const float* __restrict__ ims_W,
                               const float* __restrict__ ims_b,
                               const float* __restrict__ obs_W,
                               const float* __restrict__ obs_b,
                               const float* __restrict__ obs_out_W)
{
    int gt = blockIdx.x * blockDim.x + threadIdx.x;
    if (gt < NTI_GRU * KS_GRU * 32) {
        int lane = gt & 31;
        int ks   = (gt >> 5) % KS_GRU;
        int tile = (gt >> 5) / KS_GRU;
        int tk = lane & 3, gc = lane >> 2;
        int n = tile * 8 + gc;
        int k0 = ks * 16 + 2 * tk;
        float v[4];
#pragma unroll
        for (int e = 0; e < 4; e++) {
            int k = k0 + (e >= 2 ? 8 : 0) + (e & 1);
            float w = 0.f;
            if (n < 600) {
                if (k < 400) w = gru_W[k * 600 + n];
                else if (k == 400) w = gru_b[n];
            }
            v[e] = w;
        }
        g_WB_gru[gt] = make_uint2(h2(v[0], v[1]), h2(v[2], v[3]));
    }
    if (gt < NTI_IO * KS_IO * 32) {
        int lane = gt & 31;
        int ks   = (gt >> 5) % KS_IO;
        int tile = (gt >> 5) / KS_IO;
        int tk = lane & 3, gc = lane >> 2;
        bool is_img = tile < 25;
        int n = (is_img ? tile : tile - 25) * 8 + gc;
        int k0 = ks * 16 + 2 * tk;
        float v[4];
#pragma unroll
        for (int e = 0; e < 4; e++) {
            int k = k0 + (e >= 2 ? 8 : 0) + (e & 1);
            float w = 0.f;
            if (k < 200) w = (is_img ? img_W : obs_out_W)[k * 200 + n];
            else if (k == 200 && is_img) w = img_out_b[n];
            v[e] = w;
        }
        g_WB_io[gt] = make_uint2(h2(v[0], v[1]), h2(v[2], v[3]));
    }
    if (gt < NTI_EF * KS_EF * 32) {
        int lane = gt & 31;
        int ks   = (gt >> 5) % KS_EF;
        int tile = (gt >> 5) / KS_EF;
        int tk = lane & 3, gc = lane >> 2;
        bool is_e = tile < 8;
        int n = (is_e ? tile : tile - 8) * 8 + gc;
        int k0 = ks * 16 + 2 * tk;
        float v[4];
#pragma unroll
        for (int e = 0; e < 4; e++) {
            int k = k0 + (e >= 2 ? 8 : 0) + (e & 1);
            float w = 0.f;
            if (n < 60) {
                if (k < 200) w = (is_e ? ims_W : obs_W)[k * 60 + n];
                else if (k == 200) w = (is_e ? ims_b : obs_b)[n];
            }
            v[e] = w;
        }
        g_WB_ef[gt] = make_uint2(h2(v[0], v[1]), h2(v[2], v[3]));
    }
    if (gt < NTI_PRE * KS_PRE * 32) {
        int lane = gt & 31;
        int ks   = (gt >> 5) % KS_PRE;
        int nt   = (gt >> 5) / KS_PRE;
        int tk = lane & 3, gc = lane >> 2;
        int n = nt * 8 + gc;
        int k0 = ks * 16 + 2 * tk;
        const float* W2 = obs_out_W + (size_t)ND * NH;
        float v[4];
#pragma unroll
        for (int e = 0; e < 4; e++) {
            int k = k0 + (e >= 2 ? 8 : 0) + (e & 1);
            v[e] = W2[(size_t)k * NH + n];
        }
        g_WB_pre[gt] = make_uint2(h2(v[0], v[1]), h2(v[2], v[3]));
    }
}

// =====================================================================
// Kernel 1: precompute via HMMA. 1024 CTAs x 32 rows, 8 warps =
// 2 m-tiles x 4 n-groups (7/6/6/6 tiles).
// =====================================================================
__global__ void __launch_bounds__(256) precompute_kernel(
    const float* __restrict__ embed,
    const float* __restrict__ action,
    const float* __restrict__ obs_out_b,
    const float* __restrict__ inp_W,
    const float* __restrict__ inp_b)
{
    const int tid  = threadIdx.x;
    const int wid  = tid >> 5;
    const int lane = tid & 31;
    const int tk   = lane & 3;
    const int gr   = lane >> 2;
    const int mt   = wid & 1;
    const int ng   = wid >> 1;
    const int nt0  = (ng == 0) ? 0 : (ng == 1) ? 7 : (ng == 2) ? 13 : 19;
    const int nti  = (ng == 0) ? 7 : 6;

    const int bt0 = blockIdx.x * 32 + mt * 16;

    float acc[7][4];
#pragma unroll
    for (int i = 0; i < 7; i++)
        acc[i][0] = acc[i][1] = acc[i][2] = acc[i][3] = 0.f;

    const float2* e0 = (const float2*)(embed + (size_t)(bt0 + gr) * NE);
    const float2* e1 = (const float2*)(embed + (size_t)(bt0 + gr + 8) * NE);
    const uint2* bp = g_WB_pre + (size_t)nt0 * KS_PRE * 32 + lane;

    for (int ks = 0; ks < KS_PRE; ks++) {
        float2 f0 = e0[ks * 8 + tk];
        float2 f1 = e1[ks * 8 + tk];
        float2 f2 = e0[ks * 8 + tk + 4];
        float2 f3 = e1[ks * 8 + tk + 4];
        unsigned a0 = h2(f0.x, f0.y);
        unsigned a1 = h2(f1.x, f1.y);
        unsigned a2 = h2(f2.x, f2.y);
        unsigned a3 = h2(f3.x, f3.y);
        const uint2* bk = bp + (size_t)ks * 32;
#pragma unroll 7
        for (int i = 0; i < 7; i++) {
            if (i < nti) {
                uint2 B = bk[(size_t)i * KS_PRE * 32];
                mma16816(acc[i][0], acc[i][1], acc[i][2], acc[i][3],
                         a0, a1, a2, a3, B.x, B.y);
            }
        }
    }

#pragma unroll 7
    for (int i = 0; i < 7; i++) {
        if (i < nti) {
            int n0 = (nt0 + i) * 8 + 2 * tk;
            float b0 = obs_out_b[n0], b1 = obs_out_b[n0 + 1];
            *(float2*)&g_pre_obs[(size_t)(bt0 + gr) * NH + n0] =
                make_float2(acc[i][0] + b0, acc[i][1] + b1);
            *(float2*)&g_pre_obs[(size_t)(bt0 + gr + 8) * NH + n0] =
                make_float2(acc[i][2] + b0, acc[i][3] + b1);
        }
    }

    // ---- pre_inp (SIMT, K=12) ----
    const int base = blockIdx.x * 32;
    for (int idx = tid; idx < 32 * NH; idx += 256) {
        int rr = idx / NH, j = idx % NH;
        int bt = base + rr;
        float a = inp_b[j];
#pragma unroll
        for (int k = 0; k < NA; k++)
            a = fmaf(action[(size_t)bt * NA + k], inp_W[(NS + k) * NH + j], a);
        g_pre_inp[(size_t)bt * NH + j] = a;
    }
}

// =====================================================================
// Kernel 2: scan via HMMA, R=16 rows/CTA (full M-tile), grid 32.
// Dynamic smem. fp32 recurrent master state; biases folded as K-rows.
// =====================================================================
__global__ void __launch_bounds__(640) scan_kernel(
    const float* __restrict__ noise_prior,
    const float* __restrict__ noise_post,
    const float* __restrict__ inp_W,
    float* __restrict__ out)
{
    extern __shared__ __align__(16) char smem_raw[];
    unsigned* s_xA   = (unsigned*)(smem_raw + OFF_XA);     // [r<16][pair<216]
    unsigned* s_hA   = (unsigned*)(smem_raw + OFF_HA);     // [r][pair<116]
    unsigned* s_hoA  = (unsigned*)(smem_raw + OFF_HOA);
    float*    s_gates= (float*)(smem_raw + OFF_GATES);     // [r][608]
    float*    s_det  = (float*)(smem_raw + OFF_DET);       // [r][200]
    float*    s_stat = (float*)(smem_raw + OFF_STAT);      // [r][128]
    float*    s_pi   = (float*)(smem_raw + OFF_PI);        // [j][16]
    float*    s_po2  = (float*)(smem_raw + OFF_PO);        // [j][16]
    float*    s_stoch= (float*)(smem_raw + OFF_STOCH);     // [u][16]

    const int tid  = threadIdx.x;
    const int wid  = tid >> 5;
    const int lane = tid & 31;
    const int tk   = lane & 3;
    const int gr   = lane >> 2;
    const int row0 = blockIdx.x * R;

    for (int i = tid; i < 16 * 216; i += 640) { int p = i % 216; s_xA[i] = (p == 200) ? 0x00003C00u : 0u; }
    for (int i = tid; i < 16 * 116; i += 640) { int p = i % 116; unsigned v = (p == 100) ? 0x00003C00u : 0u; s_hA[i] = v; s_hoA[i] = v; }
    for (int i = tid; i < 16 * 200; i += 640) s_det[i] = 0.f;
    for (int i = tid; i < 32 * 16;  i += 640) s_stoch[i] = 0.f;
    for (int i = tid; i < 3200; i += 640) {
        int r = i / 200, j = i % 200;
        size_t base = ((size_t)(row0 + r) * NT + 0) * NH + j;
        s_pi [j * 16 + r] = g_pre_inp[base];
        s_po2[j * 16 + r] = g_pre_obs[base];
    }
    __syncthreads();

    for (int t = 0; t < NT; t++) {
        // ===== A: x = elu(stoch @ inp_W[:30] + pre_inp) (200 thr, fp32) =====
        if (tid < 200) {
            const int j = tid;
            ull acc[8];
            const ull* pip = (const ull*)(s_pi + j * 16);
#pragma unroll
            for (int p = 0; p < 8; p++) acc[p] = pip[p];
            for (int k = 0; k < NS; k++) {
                float w = inp_W[k * NH + j];
                ull wv = pack2(w, w);
                const ulonglong2* q = (const ulonglong2*)(s_stoch + k * 16);
                ulonglong2 v0 = q[0], v1 = q[1], v2 = q[2], v3 = q[3];
                acc[0] = fma2(v0.x, wv, acc[0]); acc[1] = fma2(v0.y, wv, acc[1]);
                acc[2] = fma2(v1.x, wv, acc[2]); acc[3] = fma2(v1.y, wv, acc[3]);
                acc[4] = fma2(v2.x, wv, acc[4]); acc[5] = fma2(v2.y, wv, acc[5]);
                acc[6] = fma2(v3.x, wv, acc[6]); acc[7] = fma2(v3.y, wv, acc[7]);
            }
            __half* xh = (__half*)s_xA;
#pragma unroll
            for (int p = 0; p < 8; p++) {
                float lo, hi; unpack2(acc[p], lo, hi);
                xh[(2 * p) * 432 + j]     = __float2half(eluf(lo));
                xh[(2 * p + 1) * 432 + j] = __float2half(eluf(hi));
            }
        }
        __syncthreads();

        // ===== B: GRU GEMM via HMMA (warps 0-18, 4 n-tiles each) =====
        if (wid < 19) {
            const int baseT = wid * 4;
            float c[4][4];
#pragma unroll
            for (int tt = 0; tt < 4; tt++)
                c[tt][0] = c[tt][1] = c[tt][2] = c[tt][3] = 0.f;
            const uint2* wb = g_WB_gru + (size_t)baseT * KS_GRU * 32 + lane;
            uint2 P0[4], P1[4];
#pragma unroll
            for (int tt = 0; tt < 4; tt++) {
                P0[tt] = wb[(size_t)tt * KS_GRU * 32 + 0 * 32];
                P1[tt] = wb[(size_t)tt * KS_GRU * 32 + 1 * 32];
            }
            for (int ks = 0; ks < KS_GRU; ks++) {
                int ksn = (ks + 2 < KS_GRU) ? ks + 2 : KS_GRU - 1;
                uint2 Pn[4];
#pragma unroll
                for (int tt = 0; tt < 4; tt++)
                    Pn[tt] = wb[(size_t)tt * KS_GRU * 32 + (size_t)ksn * 32];
                int ab0 = gr * 216 + ks * 8 + tk;
                int ab1 = (gr + 8) * 216 + ks * 8 + tk;
                unsigned a0 = s_xA[ab0];
                unsigned a1 = s_xA[ab1];
                unsigned a2 = s_xA[ab0 + 4];
                unsigned a3 = s_xA[ab1 + 4];
#pragma unroll
                for (int tt = 0; tt < 4; tt++)
                    mma16816(c[tt][0], c[tt][1], c[tt][2], c[tt][3],
                             a0, a1, a2, a3, P0[tt].x, P0[tt].y);
#pragma unroll
                for (int tt = 0; tt < 4; tt++) { P0[tt] = P1[tt]; P1[tt] = Pn[tt]; }
            }
#pragma unroll
            for (int tt = 0; tt < 4; tt++) {
                int cbase = (baseT + tt) * 8 + 2 * tk;
                *(float2*)&s_gates[gr * 608 + cbase]       = make_float2(c[tt][0], c[tt][1]);
                *(float2*)&s_gates[(gr + 8) * 608 + cbase] = make_float2(c[tt][2], c[tt][3]);
            }
        }
        __syncthreads();

        // ===== B2: gate combine -> deter_new (200 thr, fp32 master) =====
        if (tid < 200) {
            const int u = tid;
            __half* dh = (__half*)s_xA;
#pragma unroll 4
            for (int r = 0; r < R; r++) {
                float grv = s_gates[r * 608 + u];
                float gcv = s_gates[r * 608 + 200 + u];
                float guv = s_gates[r * 608 + 400 + u];
                float dold = s_det[r * 200 + u];
                float reset = sigmoidf_(grv);
                float cand  = tanhf(reset * gcv);
                float upd   = sigmoidf_(guv - 1.0f);
                float dn    = upd * cand + (1.f - upd) * dold;
                s_det[r * 200 + u] = dn;
                dh[r * 432 + 200 + u] = __float2half(dn);
                out[(((size_t)(row0 + r)) * NT + t) * OUTC + 180 + u] = dn;
            }
        }
        __syncthreads();

        // ===== C/D: h & ho via HMMA (warps 0-12, 4 n-tiles each) =====
        if (wid < 13) {
            const int baseT = wid * 4;
            float c[4][4];
#pragma unroll
            for (int tt = 0; tt < 4; tt++)
                c[tt][0] = c[tt][1] = c[tt][2] = c[tt][3] = 0.f;
            const uint2* wb = g_WB_io + (size_t)baseT * KS_IO * 32 + lane;
            uint2 P0[4], P1[4];
#pragma unroll
            for (int tt = 0; tt < 4; tt++) {
                P0[tt] = wb[(size_t)tt * KS_IO * 32 + 0 * 32];
                P1[tt] = wb[(size_t)tt * KS_IO * 32 + 1 * 32];
            }
            for (int ks = 0; ks < KS_IO; ks++) {
                int ksn = (ks + 2 < KS_IO) ? ks + 2 : KS_IO - 1;
                uint2 Pn[4];
#pragma unroll
                for (int tt = 0; tt < 4; tt++)
                    Pn[tt] = wb[(size_t)tt * KS_IO * 32 + (size_t)ksn * 32];
                int ab0 = gr * 216 + 100 + ks * 8 + tk;
                int ab1 = (gr + 8) * 216 + 100 + ks * 8 + tk;
                unsigned a0 = s_xA[ab0];
                unsigned a1 = s_xA[ab1];
                unsigned a2 = s_xA[ab0 + 4];
                unsigned a3 = s_xA[ab1 + 4];
#pragma unroll
                for (int tt = 0; tt < 4; tt++)
                    mma16816(c[tt][0], c[tt][1], c[tt][2], c[tt][3],
                             a0, a1, a2, a3, P0[tt].x, P0[tt].y);
#pragma unroll
                for (int tt = 0; tt < 4; tt++) { P0[tt] = P1[tt]; P1[tt] = Pn[tt]; }
            }
#pragma unroll
            for (int tt = 0; tt < 4; tt++) {
                int tile = baseT + tt;
                if (tile < 50) {
                    if (tile < 25) {
                        int p = tile * 4 + tk;
                        s_hA[gr * 116 + p]       = h2(eluf(c[tt][0]), eluf(c[tt][1]));
                        s_hA[(gr + 8) * 116 + p] = h2(eluf(c[tt][2]), eluf(c[tt][3]));
                    } else {
                        int tl = tile - 25;
                        int j  = tl * 8 + 2 * tk;
                        int p  = tl * 4 + tk;
                        float o0 = eluf(c[tt][0] + s_po2[j * 16 + gr]);
                        float o1 = eluf(c[tt][1] + s_po2[(j + 1) * 16 + gr]);
                        s_hoA[gr * 116 + p] = h2(o0, o1);
                        float o2 = eluf(c[tt][2] + s_po2[j * 16 + gr + 8]);
                        float o3 = eluf(c[tt][3] + s_po2[(j + 1) * 16 + gr + 8]);
                        s_hoA[(gr + 8) * 116 + p] = h2(o2, o3);
                    }
                }
            }
        }
        __syncthreads();

        // ===== E/F via HMMA (warps 0-15) + stage t+1 (warps 16-19) =====
        if (wid < 16) {
            const bool is_e = wid < 8;
            const unsigned* aA = is_e ? s_hA : s_hoA;
            const uint2* wb = g_WB_ef + (size_t)wid * KS_EF * 32 + lane;
            float c0 = 0.f, c1 = 0.f, c2 = 0.f, c3 = 0.f;
            uint2 P0 = wb[0], P1 = wb[32];
            for (int ks = 0; ks < KS_EF; ks++) {
                int ksn = (ks + 2 < KS_EF) ? ks + 2 : KS_EF - 1;
                uint2 Pn = wb[(size_t)ksn * 32];
                int ab0 = gr * 116 + ks * 8 + tk;
                int ab1 = (gr + 8) * 116 + ks * 8 + tk;
                unsigned a0 = aA[ab0];
                unsigned a1 = aA[ab1];
                unsigned a2 = aA[ab0 + 4];
                unsigned a3 = aA[ab1 + 4];
                mma16816(c0, c1, c2, c3, a0, a1, a2, a3, P0.x, P0.y);
                P0 = P1; P1 = Pn;
            }
            int cc = (wid & 7) * 8 + 2 * tk;
            int off = is_e ? 0 : 64;
            *(float2*)&s_stat[gr * 128 + off + cc]       = make_float2(c0, c1);
            *(float2*)&s_stat[(gr + 8) * 128 + off + cc] = make_float2(c2, c3);
        } else if (t + 1 < NT) {
            for (int i = tid - 512; i < 3200; i += 128) {
                int r = i / 200, j = i % 200;
                size_t base = ((size_t)(row0 + r) * NT + (t + 1)) * NH + j;
                s_pi [j * 16 + r] = g_pre_inp[base];
                s_po2[j * 16 + r] = g_pre_obs[base];
            }
        }
        __syncthreads();

        // ===== finalize: sample, write, carry =====
        if (tid < NS) {
            const int u = tid;
#pragma unroll 4
            for (int r = 0; r < R; r++) {
                float m  = s_stat[r * 128 + u];
                float sd = softplusf_(s_stat[r * 128 + 30 + u]) + 0.1f;
                size_t bt = ((size_t)(row0 + r)) * NT + t;
                float nz = noise_prior[bt * NS + u];
                size_t ob = bt * OUTC;
                out[ob + 120 + u] = m;
                out[ob + 150 + u] = sd;
                out[ob +  90 + u] = m + sd * nz;
            }
        } else if (tid >= 32 && tid < 32 + NS) {
            const int u = tid - 32;
#pragma unroll 4
            for (int r = 0; r < R; r++) {
                float m  = s_stat[r * 128 + 64 + u];
                float sd = softplusf_(s_stat[r * 128 + 94 + u]) + 0.1f;
                size_t bt = ((size_t)(row0 + r)) * NT + t;
                float nz = noise_post[bt * NS + u];
                float st = m + sd * nz;
                size_t ob = bt * OUTC;
                out[ob + 30 + u] = m;
                out[ob + 60 + u] = sd;
                out[ob +  0 + u] = st;
                s_stoch[u * 16 + r] = st;
            }
        }
        __syncthreads();
    }
}

// =====================================================================
extern "C" void kernel_launch(void* const* d_in, const int* in_sizes, int n_in,
                              void* d_out, int out_size) {
    const float* embed       = (const float*)d_in[0];
    const float* action      = (const float*)d_in[1];
    const float* noise_prior = (const float*)d_in[2];
    const float* noise_post  = (const float*)d_in[3];
    const float* inp_W       = (const float*)d_in[4];
    const float* inp_b       = (const float*)d_in[5];
    const float* gru_W       = (const float*)d_in[6];
    const float* gru_b       = (const float*)d_in[7];
    const float* img_out_W   = (const float*)d_in[8];
    const float* img_out_b   = (const float*)d_in[9];
    const float* ims_W       = (const float*)d_in[10];
    const float* ims_b       = (const float*)d_in[11];
    const float* obs_out_W   = (const float*)d_in[12];
    const float* obs_out_b   = (const float*)d_in[13];
    const float* obs_W       = (const float*)d_in[14];
    const float* obs_b       = (const float*)d_in[15];
    float* out = (float*)d_out;

    static bool attr_set = false;
    if (!attr_set) {
        cudaFuncSetAttribute(scan_kernel,
                             cudaFuncAttributeMaxDynamicSharedMemorySize, SMEM_BYTES);
        attr_set = true;
    }

    convert_kernel<<<(NTI_GRU * KS_GRU * 32 + 255) / 256, 256>>>(
        gru_W, gru_b, img_out_W, img_out_b, ims_W, ims_b, obs_W, obs_b, obs_out_W);
    precompute_kernel<<<(NB * NT) / 32, 256>>>(embed, action, obs_out_b, inp_W, inp_b);
    scan_kernel<<<NCTA, 640, SMEM_BYTES>>>(noise_prior, noise_post, inp_W, out);
}

// round 17
// speedup vs baseline: 2.6304x; 2.6304x over previous
#include <cuda_runtime.h>
#include <cuda_fp16.h>
#include <math.h>

#define NB 512
#define NT 64
#define NS 30
#define ND 200
#define NH 200
#define NA 12
#define NE 1024
#define OUTC 380
#define R 4
#define NCTA (NB / R)   // 128

// MMA tilings (m16n8k16)
#define KS_GRU 26
#define NTI_GRU 76
#define KS_IO  14
#define NTI_IO 50
#define KS_EF  14
#define NTI_EF 16
#define KS_PRE 64
#define NTI_PRE 25

// ---------------- device-global scratch (allocation-free rule) ----------------
__device__ __align__(16) uint2 g_WB_gru[NTI_GRU * KS_GRU * 32];
__device__ __align__(16) uint2 g_WB_io [NTI_IO  * KS_IO  * 32];
__device__ __align__(16) uint2 g_WB_ef [NTI_EF  * KS_EF  * 32];
__device__ __align__(16) uint2 g_WB_pre[NTI_PRE * KS_PRE * 32];
__device__ float g_pre_inp[NB * NT * NH];
__device__ float g_pre_obs[NB * NT * NH];

typedef unsigned long long ull;

// ---------------- helpers ----------------
__device__ __forceinline__ unsigned h2(float a, float b) {
    __half2 h = __floats2half2_rn(a, b);
    return *(unsigned*)&h;
}
__device__ __forceinline__ void mma16816(float& c0, float& c1, float& c2, float& c3,
                                         unsigned a0, unsigned a1, unsigned a2, unsigned a3,
                                         unsigned b0, unsigned b1) {
    asm volatile(
        "mma.sync.aligned.m16n8k16.row.col.f32.f16.f16.f32 "
        "{%0,%1,%2,%3},{%4,%5,%6,%7},{%8,%9},{%0,%1,%2,%3};"
        : "+f"(c0), "+f"(c1), "+f"(c2), "+f"(c3)
        : "r"(a0), "r"(a1), "r"(a2), "r"(a3), "r"(b0), "r"(b1));
}
__device__ __forceinline__ float eluf(float z)      { return z > 0.f ? z : expm1f(z); }
__device__ __forceinline__ float sigmoidf_(float z) { return 1.f / (1.f + expf(-z)); }
__device__ __forceinline__ float softplusf_(float z){ return fmaxf(z, 0.f) + log1pf(expf(-fabsf(z))); }

// =====================================================================
// Kernel 0: pack ALL weights into HMMA B-fragment lane order
// =====================================================================
__global__ void convert_kernel(const float* __restrict__ gru_W,
                               const float* __restrict__ gru_b,
                               const float* __restrict__ img_W,
                               const float* __restrict__ img_out_b,
                               const float* __restrict__ ims_W,
                               const float* __restrict__ ims_b,
                               const float* __restrict__ obs_W,
                               const float* __restrict__ obs_b,
                               const float* __restrict__ obs_out_W)
{
    int gt = blockIdx.x * blockDim.x + threadIdx.x;
    if (gt < NTI_GRU * KS_GRU * 32) {
        int lane = gt & 31;
        int ks   = (gt >> 5) % KS_GRU;
        int tile = (gt >> 5) / KS_GRU;
        int tk = lane & 3, gc = lane >> 2;
        int n = tile * 8 + gc;
        int k0 = ks * 16 + 2 * tk;
        float v[4];
#pragma unroll
        for (int e = 0; e < 4; e++) {
            int k = k0 + (e >= 2 ? 8 : 0) + (e & 1);
            float w = 0.f;
            if (n < 600) {
                if (k < 400) w = gru_W[k * 600 + n];
                else if (k == 400) w = gru_b[n];
            }
            v[e] = w;
        }
        g_WB_gru[gt] = make_uint2(h2(v[0], v[1]), h2(v[2], v[3]));
    }
    if (gt < NTI_IO * KS_IO * 32) {
        int lane = gt & 31;
        int ks   = (gt >> 5) % KS_IO;
        int tile = (gt >> 5) / KS_IO;
        int tk = lane & 3, gc = lane >> 2;
        bool is_img = tile < 25;
        int n = (is_img ? tile : tile - 25) * 8 + gc;
        int k0 = ks * 16 + 2 * tk;
        float v[4];
#pragma unroll
        for (int e = 0; e < 4; e++) {
            int k = k0 + (e >= 2 ? 8 : 0) + (e & 1);
            float w = 0.f;
            if (k < 200) w = (is_img ? img_W : obs_out_W)[k * 200 + n];
            else if (k == 200 && is_img) w = img_out_b[n];
            v[e] = w;
        }
        g_WB_io[gt] = make_uint2(h2(v[0], v[1]), h2(v[2], v[3]));
    }
    if (gt < NTI_EF * KS_EF * 32) {
        int lane = gt & 31;
        int ks   = (gt >> 5) % KS_EF;
        int tile = (gt >> 5) / KS_EF;
        int tk = lane & 3, gc = lane >> 2;
        bool is_e = tile < 8;
        int n = (is_e ? tile : tile - 8) * 8 + gc;
        int k0 = ks * 16 + 2 * tk;
        float v[4];
#pragma unroll
        for (int e = 0; e < 4; e++) {
            int k = k0 + (e >= 2 ? 8 : 0) + (e & 1);
            float w = 0.f;
            if (n < 60) {
                if (k < 200) w = (is_e ? ims_W : obs_W)[k * 60 + n];
                else if (k == 200) w = (is_e ? ims_b : obs_b)[n];
            }
            v[e] = w;
        }
        g_WB_ef[gt] = make_uint2(h2(v[0], v[1]), h2(v[2], v[3]));
    }
    if (gt < NTI_PRE * KS_PRE * 32) {
        int lane = gt & 31;
        int ks   = (gt >> 5) % KS_PRE;
        int nt   = (gt >> 5) / KS_PRE;
        int tk = lane & 3, gc = lane >> 2;
        int n = nt * 8 + gc;
        int k0 = ks * 16 + 2 * tk;
        const float* W2 = obs_out_W + (size_t)ND * NH;
        float v[4];
#pragma unroll
        for (int e = 0; e < 4; e++) {
            int k = k0 + (e >= 2 ? 8 : 0) + (e & 1);
            v[e] = W2[(size_t)k * NH + n];
        }
        g_WB_pre[gt] = make_uint2(h2(v[0], v[1]), h2(v[2], v[3]));
    }
}

// =====================================================================
// Kernel 1: precompute via HMMA with depth-2 software pipeline.
// 512 CTAs x 64 bt-rows; 8 warps = 4 m-tiles x 2 n-groups.
// =====================================================================
__global__ void __launch_bounds__(256) precompute_kernel(
    const float* __restrict__ embed,
    const float* __restrict__ action,
    const float* __restrict__ obs_out_b,
    const float* __restrict__ inp_W,
    const float* __restrict__ inp_b)
{
    const int tid  = threadIdx.x;
    const int wid  = tid >> 5;
    const int lane = tid & 31;
    const int tk   = lane & 3;
    const int gr   = lane >> 2;
    const int mt   = wid & 3;
    const int ng   = wid >> 2;
    const int nt0  = ng ? 13 : 0;
    const int nti  = ng ? 12 : 13;

    const int bt0 = blockIdx.x * 64 + mt * 16;

    float acc[13][4];
#pragma unroll
    for (int i = 0; i < 13; i++)
        acc[i][0] = acc[i][1] = acc[i][2] = acc[i][3] = 0.f;

    const float2* e0 = (const float2*)(embed + (size_t)(bt0 + gr) * NE);
    const float2* e1 = (const float2*)(embed + (size_t)(bt0 + gr + 8) * NE);
    const uint2* bp = g_WB_pre + (size_t)nt0 * KS_PRE * 32 + lane;

    // depth-2 pipeline state
    float2 ec0 = e0[tk], ec1 = e1[tk], ec2 = e0[tk + 4], ec3 = e1[tk + 4];
    uint2 Bc[13];
#pragma unroll 13
    for (int i = 0; i < 13; i++)
        if (i < nti) Bc[i] = bp[(size_t)i * KS_PRE * 32];

    for (int ks = 0; ks < KS_PRE; ks++) {
        int ksn = (ks + 1 < KS_PRE) ? ks + 1 : ks;
        // prefetch next iteration
        float2 en0 = e0[ksn * 8 + tk];
        float2 en1 = e1[ksn * 8 + tk];
        float2 en2 = e0[ksn * 8 + tk + 4];
        float2 en3 = e1[ksn * 8 + tk + 4];
        uint2 Bn[13];
        const uint2* bk = bp + (size_t)ksn * 32;
#pragma unroll 13
        for (int i = 0; i < 13; i++)
            if (i < nti) Bn[i] = bk[(size_t)i * KS_PRE * 32];
        // compute current
        unsigned a0 = h2(ec0.x, ec0.y);
        unsigned a1 = h2(ec1.x, ec1.y);
        unsigned a2 = h2(ec2.x, ec2.y);
        unsigned a3 = h2(ec3.x, ec3.y);
#pragma unroll 13
        for (int i = 0; i < 13; i++) {
            if (i < nti)
                mma16816(acc[i][0], acc[i][1], acc[i][2], acc[i][3],
                         a0, a1, a2, a3, Bc[i].x, Bc[i].y);
        }
        ec0 = en0; ec1 = en1; ec2 = en2; ec3 = en3;
#pragma unroll 13
        for (int i = 0; i < 13; i++)
            if (i < nti) Bc[i] = Bn[i];
    }

#pragma unroll 13
    for (int i = 0; i < 13; i++) {
        if (i < nti) {
            int n0 = (nt0 + i) * 8 + 2 * tk;
            float b0 = obs_out_b[n0], b1 = obs_out_b[n0 + 1];
            *(float2*)&g_pre_obs[(size_t)(bt0 + gr) * NH + n0] =
                make_float2(acc[i][0] + b0, acc[i][1] + b1);
            *(float2*)&g_pre_obs[(size_t)(bt0 + gr + 8) * NH + n0] =
                make_float2(acc[i][2] + b0, acc[i][3] + b1);
        }
    }

    // ---- pre_inp (SIMT, K=12) ----
    const int base = blockIdx.x * 64;
    for (int idx = tid; idx < 64 * NH; idx += 256) {
        int rr = idx / NH, j = idx % NH;
        int bt = base + rr;
        float a = inp_b[j];
#pragma unroll
        for (int k = 0; k < NA; k++)
            a = fmaf(action[(size_t)bt * NA + k], inp_W[(NS + k) * NH + j], a);
        g_pre_inp[(size_t)bt * NH + j] = a;
    }
}

// =====================================================================
// Kernel 2: scan via HMMA (R15 structure) + cross-barrier weight
// prefetch: each phase's initial ring fill is issued in the previous
// phase's block so the L2-latency head stall is hidden by the barrier.
// =====================================================================
__global__ void __launch_bounds__(640) scan_kernel(
    const float* __restrict__ noise_prior,
    const float* __restrict__ noise_post,
    const float* __restrict__ inp_W,
    float* __restrict__ out)
{
    __shared__ __align__(16) unsigned s_xA [4 * 216];
    __shared__ __align__(16) unsigned s_hA [4 * 116];
    __shared__ __align__(16) unsigned s_hoA[4 * 116];
    __shared__ __align__(16) float s_gates[4 * 608];
    __shared__ __align__(16) float s_det  [4 * 200];
    __shared__ __align__(16) float s_stat [4 * 128];
    __shared__ __align__(16) float s_pi [800];
    __shared__ __align__(16) float s_po2[800];
    __shared__ __align__(16) float s_stoch[128];

    const int tid  = threadIdx.x;
    const int wid  = tid >> 5;
    const int lane = tid & 31;
    const int tk   = lane & 3;
    const int gr   = lane >> 2;
    const int row0 = blockIdx.x * R;

    for (int i = tid; i < 4 * 216; i += 640) { int p = i % 216; s_xA[i] = (p == 200) ? 0x00003C00u : 0u; }
    for (int i = tid; i < 4 * 116; i += 640) { int p = i % 116; unsigned v = (p == 100) ? 0x00003C00u : 0u; s_hA[i] = v; s_hoA[i] = v; }
    for (int i = tid; i < 800; i += 640) s_det[i] = 0.f;
    for (int i = tid; i < 128; i += 640) s_stoch[i] = 0.f;
    for (int i = tid; i < 800; i += 640) {
        int j = i >> 2, r = i & 3;
        size_t base = ((size_t)(row0 + r) * NT + 0) * NH + j;
        s_pi [i] = g_pre_inp[base];
        s_po2[i] = g_pre_obs[base];
    }
    __syncthreads();

    const uint2* wb_gru = (wid < 19) ? g_WB_gru + (size_t)(wid * 4) * KS_GRU * 32 + lane : g_WB_gru;
    const uint2* wb_io  = (wid < 13) ? g_WB_io  + (size_t)(wid * 4) * KS_IO  * 32 + lane : g_WB_io;
    const uint2* wb_ef  = (wid < 16) ? g_WB_ef  + (size_t)wid * KS_EF * 32 + lane : g_WB_ef;

    for (int t = 0; t < NT; t++) {
        // ---- prefetch B ring (issued before A; warps 7-18 idle during A) ----
        uint2 Pb0[4], Pb1[4];
        if (wid < 19) {
#pragma unroll
            for (int tt = 0; tt < 4; tt++) {
                Pb0[tt] = wb_gru[(size_t)tt * KS_GRU * 32];
                Pb1[tt] = wb_gru[(size_t)tt * KS_GRU * 32 + 32];
            }
        }

        // ===== A: x = elu(stoch @ inp_W[:30] + pre_inp) (200 thr, fp32) =====
        if (tid < 200) {
            const int j = tid;
            float4 acc = *(const float4*)&s_pi[j * 4];
#pragma unroll
            for (int k = 0; k < NS; k++) {
                float w = inp_W[k * NH + j];
                acc.x = fmaf(w, s_stoch[0 * 32 + k], acc.x);
                acc.y = fmaf(w, s_stoch[1 * 32 + k], acc.y);
                acc.z = fmaf(w, s_stoch[2 * 32 + k], acc.z);
                acc.w = fmaf(w, s_stoch[3 * 32 + k], acc.w);
            }
            __half* xh = (__half*)s_xA;
            int half_idx = (j >> 1) * 2 + (j & 1);
            xh[(0 * 216) * 2 + half_idx] = __float2half(eluf(acc.x));
            xh[(1 * 216) * 2 + half_idx] = __float2half(eluf(acc.y));
            xh[(2 * 216) * 2 + half_idx] = __float2half(eluf(acc.z));
            xh[(3 * 216) * 2 + half_idx] = __float2half(eluf(acc.w));
        }
        __syncthreads();

        // ===== B: GRU GEMM via HMMA (warps 0-18, 4 n-tiles each) =====
        uint2 Pi0[4], Pi1[4];   // C/D ring (filled at end of this block)
        if (wid < 19) {
            float c[4][4];
#pragma unroll
            for (int tt = 0; tt < 4; tt++)
                c[tt][0] = c[tt][1] = c[tt][2] = c[tt][3] = 0.f;
            for (int ks = 0; ks < KS_GRU; ks++) {
                int ksn = (ks + 2 < KS_GRU) ? ks + 2 : KS_GRU - 1;
                uint2 Pn[4];
#pragma unroll
                for (int tt = 0; tt < 4; tt++)
                    Pn[tt] = wb_gru[(size_t)tt * KS_GRU * 32 + (size_t)ksn * 32];
                unsigned a0 = 0, a2 = 0;
                if (gr < 4) {
                    int ab = gr * 216 + ks * 8 + tk;
                    a0 = s_xA[ab];
                    a2 = s_xA[ab + 4];
                }
#pragma unroll
                for (int tt = 0; tt < 4; tt++)
                    mma16816(c[tt][0], c[tt][1], c[tt][2], c[tt][3],
                             a0, 0u, a2, 0u, Pb0[tt].x, Pb0[tt].y);
#pragma unroll
                for (int tt = 0; tt < 4; tt++) { Pb0[tt] = Pb1[tt]; Pb1[tt] = Pn[tt]; }
            }
            if (gr < 4) {
#pragma unroll
                for (int tt = 0; tt < 4; tt++) {
                    int cbase = (wid * 4 + tt) * 8 + 2 * tk;
                    *(float2*)&s_gates[gr * 608 + cbase] = make_float2(c[tt][0], c[tt][1]);
                }
            }
        }
        // prefetch C/D ring (2 barriers of lead time)
        if (wid < 13) {
#pragma unroll
            for (int tt = 0; tt < 4; tt++) {
                Pi0[tt] = wb_io[(size_t)tt * KS_IO * 32];
                Pi1[tt] = wb_io[(size_t)tt * KS_IO * 32 + 32];
            }
        }
        __syncthreads();

        // ===== B2: gate combine -> deter_new (200 thr, fp32 master) =====
        if (tid < 200) {
            const int u = tid;
            __half* dh = (__half*)s_xA;
            int half_idx = (100 + (u >> 1)) * 2 + (u & 1);
#pragma unroll
            for (int r = 0; r < R; r++) {
                float grv = s_gates[r * 608 + u];
                float gcv = s_gates[r * 608 + 200 + u];
                float guv = s_gates[r * 608 + 400 + u];
                float dold = s_det[r * 200 + u];
                float reset = sigmoidf_(grv);
                float cand  = tanhf(reset * gcv);
                float upd   = sigmoidf_(guv - 1.0f);
                float dn    = upd * cand + (1.f - upd) * dold;
                s_det[r * 200 + u] = dn;
                dh[r * 216 * 2 + half_idx] = __float2half(dn);
                out[(((size_t)(row0 + r)) * NT + t) * OUTC + 180 + u] = dn;
            }
        }
        __syncthreads();

        // ===== C/D: h & ho via HMMA (warps 0-12, 4 n-tiles each) =====
        uint2 Pe0, Pe1;         // E/F ring (filled at end of this block)
        if (wid < 13) {
            float c[4][4];
#pragma unroll
            for (int tt = 0; tt < 4; tt++)
                c[tt][0] = c[tt][1] = c[tt][2] = c[tt][3] = 0.f;
            for (int ks = 0; ks < KS_IO; ks++) {
                int ksn = (ks + 2 < KS_IO) ? ks + 2 : KS_IO - 1;
                uint2 Pn[4];
#pragma unroll
                for (int tt = 0; tt < 4; tt++)
                    Pn[tt] = wb_io[(size_t)tt * KS_IO * 32 + (size_t)ksn * 32];
                unsigned a0 = 0, a2 = 0;
                if (gr < 4) {
                    int ab = gr * 216 + 100 + ks * 8 + tk;
                    a0 = s_xA[ab];
                    a2 = s_xA[ab + 4];
                }
#pragma unroll
                for (int tt = 0; tt < 4; tt++)
                    mma16816(c[tt][0], c[tt][1], c[tt][2], c[tt][3],
                             a0, 0u, a2, 0u, Pi0[tt].x, Pi0[tt].y);
#pragma unroll
                for (int tt = 0; tt < 4; tt++) { Pi0[tt] = Pi1[tt]; Pi1[tt] = Pn[tt]; }
            }
            if (gr < 4) {
#pragma unroll
                for (int tt = 0; tt < 4; tt++) {
                    int tile = wid * 4 + tt;
                    if (tile < 50) {
                        if (tile < 25) {
                            int p = tile * 4 + tk;
                            s_hA[gr * 116 + p] = h2(eluf(c[tt][0]), eluf(c[tt][1]));
                        } else {
                            int tl = tile - 25;
                            int j  = tl * 8 + 2 * tk;
                            int p  = tl * 4 + tk;
                            float o0 = eluf(c[tt][0] + s_po2[j * 4 + gr]);
                            float o1 = eluf(c[tt][1] + s_po2[(j + 1) * 4 + gr]);
                            s_hoA[gr * 116 + p] = h2(o0, o1);
                        }
                    }
                }
            }
        }
        // prefetch E/F ring
        if (wid < 16) {
            Pe0 = wb_ef[0];
            Pe1 = wb_ef[32];
        }
        __syncthreads();

        // ===== E/F via HMMA (warps 0-15) + stage t+1 (warps 16-19) =====
        if (wid < 16) {
            const bool is_e = wid < 8;
            const unsigned* aA = is_e ? s_hA : s_hoA;
            float c0 = 0.f, c1 = 0.f, c2 = 0.f, c3 = 0.f;
            for (int ks = 0; ks < KS_EF; ks++) {
                int ksn = (ks + 2 < KS_EF) ? ks + 2 : KS_EF - 1;
                uint2 Pn = wb_ef[(size_t)ksn * 32];
                unsigned a0 = 0, a2 = 0;
                if (gr < 4) {
                    int ab = gr * 116 + ks * 8 + tk;
                    a0 = aA[ab];
                    a2 = aA[ab + 4];
                }
                mma16816(c0, c1, c2, c3, a0, 0u, a2, 0u, Pe0.x, Pe0.y);
                Pe0 = Pe1; Pe1 = Pn;
            }
            if (gr < 4) {
                int cc = (wid & 7) * 8 + 2 * tk;
                int off = is_e ? 0 : 64;
                *(float2*)&s_stat[gr * 128 + off + cc] = make_float2(c0, c1);
            }
        } else if (t + 1 < NT) {
            for (int i = tid - 512; i < 800; i += 128) {
                int j = i >> 2, r = i & 3;
                size_t base = ((size_t)(row0 + r) * NT + (t + 1)) * NH + j;
                s_pi [i] = g_pre_inp[base];
                s_po2[i] = g_pre_obs[base];
            }
        }
        __syncthreads();

        // ===== finalize: sample, write, carry =====
        if (tid < NS) {
            const int u = tid;
#pragma unroll
            for (int r = 0; r < R; r++) {
                float m  = s_stat[r * 128 + u];
                float sd = softplusf_(s_stat[r * 128 + 30 + u]) + 0.1f;
                size_t bt = ((size_t)(row0 + r)) * NT + t;
                float nz = noise_prior[bt * NS + u];
                size_t ob = bt * OUTC;
                out[ob + 120 + u] = m;
                out[ob + 150 + u] = sd;
                out[ob +  90 + u] = m + sd * nz;
            }
        } else if (tid >= 32 && tid < 32 + NS) {
            const int u = tid - 32;
#pragma unroll
            for (int r = 0; r < R; r++) {
                float m  = s_stat[r * 128 + 64 + u];
                float sd = softplusf_(s_stat[r * 128 + 94 + u]) + 0.1f;
                size_t bt = ((size_t)(row0 + r)) * NT + t;
                float nz = noise_post[bt * NS + u];
                float st = m + sd * nz;
                size_t ob = bt * OUTC;
                out[ob + 30 + u] = m;
                out[ob + 60 + u] = sd;
                out[ob +  0 + u] = st;
                s_stoch[r * 32 + u] = st;
            }
        }
        __syncthreads();
    }
}

// =====================================================================
extern "C" void kernel_launch(void* const* d_in, const int* in_sizes, int n_in,
                              void* d_out, int out_size) {
    const float* embed       = (const float*)d_in[0];
    const float* action      = (const float*)d_in[1];
    const float* noise_prior = (const float*)d_in[2];
    const float* noise_post  = (const float*)d_in[3];
    const float* inp_W       = (const float*)d_in[4];
    const float* inp_b       = (const float*)d_in[5];
    const float* gru_W       = (const float*)d_in[6];
    const float* gru_b       = (const float*)d_in[7];
    const float* img_out_W   = (const float*)d_in[8];
    const float* img_out_b   = (const float*)d_in[9];
    const float* ims_W       = (const float*)d_in[10];
    const float* ims_b       = (const float*)d_in[11];
    const float* obs_out_W   = (const float*)d_in[12];
    const float* obs_out_b   = (const float*)d_in[13];
    const float* obs_W       = (const float*)d_in[14];
    const float* obs_b       = (const float*)d_in[15];
    float* out = (float*)d_out;

    convert_kernel<<<(NTI_GRU * KS_GRU * 32 + 255) / 256, 256>>>(
        gru_W, gru_b, img_out_W, img_out_b, ims_W, ims_b, obs_W, obs_b, obs_out_W);
    precompute_kernel<<<(NB * NT) / 64, 256>>>(embed, action, obs_out_b, inp_W, inp_b);
    scan_kernel<<<NCTA, 640>>>(noise_prior, noise_post, inp_W, out);
}